// round 1
// baseline (speedup 1.0000x reference)
#include <cuda_runtime.h>

#define Bb 32
#define Nn 512
#define Mm 512
#define KD 64
#define NDIAG 1023            // anti-diagonals s = i'+j' in [0, 1022]
#define BIGV 1e10f

// Skewed cost matrix: Danti[b][s][i'] = D[b][i'][s-i'], s = i'+j'
// 32 * 1023 * 512 * 4B = 67 MB (fits in L2 for the producer->consumer handoff)
__device__ float g_Danti[(size_t)Bb * NDIAG * 512];

// ---------------------------------------------------------------------------
// Kernel 1: cost matrix, 64x64 tiles, K=64 in one shot, write skewed+coalesced
// ---------------------------------------------------------------------------
__global__ __launch_bounds__(256) void cost_kernel(const float* __restrict__ X,
                                                   const float* __restrict__ Y) {
    // Shared reused: phase A = Xs[64][68] + Ys[64][68]; phase B = Ds[127][65]
    __shared__ float sm[2 * 64 * 68];   // 8704 floats = 34.8 KB
    float* Xs = sm;                     // pitch 68 (float4-aligned, 2-way bank ok)
    float* Ys = sm + 64 * 68;
    float* Ds = sm;                     // 127*65 = 8255 floats, reuses the same smem

    const int I0 = blockIdx.x * 64;
    const int J0 = blockIdx.y * 64;
    const int b  = blockIdx.z;
    const int tid = threadIdx.x;

    // ---- load X tile [I0..I0+63][0..63] and Y tile, float4 coalesced ----
    {
        int lr = tid >> 4;          // 0..15
        int lc = (tid & 15) * 4;    // 0,4,...,60
        #pragma unroll
        for (int rr = 0; rr < 64; rr += 16) {
            float4 vx = *(const float4*)&X[((size_t)(b * Nn + I0 + lr + rr)) * KD + lc];
            *(float4*)&Xs[(lr + rr) * 68 + lc] = vx;
            float4 vy = *(const float4*)&Y[((size_t)(b * Mm + J0 + lr + rr)) * KD + lc];
            *(float4*)&Ys[(lr + rr) * 68 + lc] = vy;
        }
    }
    __syncthreads();

    // ---- compute 4x4 micro-tile per thread: D = sum_k (x_k - y_k)^2 ----
    const int ty4 = (tid >> 4) * 4;   // row base
    const int tx4 = (tid & 15) * 4;   // col base
    float acc[4][4];
    #pragma unroll
    for (int r = 0; r < 4; r++)
        #pragma unroll
        for (int c = 0; c < 4; c++) acc[r][c] = 0.f;

    #pragma unroll 4
    for (int k = 0; k < KD; k++) {
        float a[4], bv[4];
        #pragma unroll
        for (int r = 0; r < 4; r++) a[r] = Xs[(ty4 + r) * 68 + k];
        #pragma unroll
        for (int c = 0; c < 4; c++) bv[c] = Ys[(tx4 + c) * 68 + k];
        #pragma unroll
        for (int r = 0; r < 4; r++)
            #pragma unroll
            for (int c = 0; c < 4; c++) {
                float dlt = a[r] - bv[c];
                acc[r][c] = fmaf(dlt, dlt, acc[r][c]);
            }
    }
    __syncthreads();   // all smem reads done -> safe to overwrite with Ds

    // ---- scatter into skewed smem tile: Ds[li+lj][li] ----
    #pragma unroll
    for (int r = 0; r < 4; r++)
        #pragma unroll
        for (int c = 0; c < 4; c++) {
            int li = ty4 + r, lj = tx4 + c;
            Ds[(li + lj) * 65 + li] = acc[r][c];
        }
    __syncthreads();

    // ---- coalesced write of diagonal segments to global skewed layout ----
    const size_t gbase = (size_t)b * NDIAG * 512;
    const int S0 = I0 + J0;
    for (int idx = tid; idx < 127 * 64; idx += 256) {
        int s  = idx >> 6;
        int li = idx & 63;
        int lj = s - li;
        if (lj >= 0 && lj < 64) {
            g_Danti[gbase + (size_t)(S0 + s) * 512 + (I0 + li)] = Ds[s * 65 + li];
        }
    }
}

// ---------------------------------------------------------------------------
// Kernel 2: anti-diagonal wavefront DP, one CTA per batch, 512 threads
// thread ti owns row i = ti+1; R arrays indexed by i in [0, 512]
// ---------------------------------------------------------------------------
__global__ __launch_bounds__(512) void dp_kernel(const int* __restrict__ Xl,
                                                 const int* __restrict__ Yl,
                                                 float* __restrict__ out) {
    __shared__ float buf[3][520];   // 3 rotating diagonals, padded

    const int b  = blockIdx.x;
    const int ti = threadIdx.x;     // 0..511
    const int i  = ti + 1;

    const int td = Xl[b] + Yl[b];   // target diagonal d = X_len + Y_len
    const int it = Xl[b];           // target row index i = X_len

    // diag 0: R[0,0]=0, rest BIG ; diag 1: all BIG
    buf[0][i] = BIGV;
    buf[1][i] = BIGV;
    if (ti == 0) { buf[0][0] = 0.f; buf[1][0] = BIGV; }
    __syncthreads();

    float* r2 = buf[0];
    float* r1 = buf[1];
    float* rc = buf[2];

    const float* Dbase = g_Danti + (size_t)b * NDIAG * 512 + ti;

    // software prefetch of D across the barrier boundary
    float Dv = Dbase[0];            // for d = 2 (s = 0)

    for (int d = 2; d <= Nn + Mm; ++d) {
        // prefetch D for next diagonal (clamped to stay in bounds on last iter)
        int sn = min(d - 1, NDIAG - 1);
        float Dnext = Dbase[(size_t)sn * 512];

        int j = d - i;
        float a  = r2[ti];          // R[i-1, j-1]
        float bt = r1[ti];          // R[i-1, j]
        float cl = r1[i];           // R[i,   j-1]

        float m   = fminf(a, fminf(bt, cl));
        float sum = __expf(m - a) + __expf(m - bt) + __expf(m - cl);
        float soft = m - __logf(sum);           // -gamma * lse(-z/gamma), gamma=1
        float val = (j >= 1 && j <= Mm) ? (Dv + soft) : BIGV;

        rc[i] = val;
        if (ti == 0) rc[0] = BIGV;              // border R[0, d] = BIG
        if (d == td && i == it) out[b] = val;   // loss[b] = R[X_len, Y_len]

        __syncthreads();

        // rotate diagonals
        float* t = r2; r2 = r1; r1 = rc; rc = t;
        Dv = Dnext;
    }
}

// ---------------------------------------------------------------------------
extern "C" void kernel_launch(void* const* d_in, const int* in_sizes, int n_in,
                              void* d_out, int out_size) {
    const float* X  = (const float*)d_in[0];
    const float* Y  = (const float*)d_in[1];
    const int*   Xl = (const int*)d_in[2];
    const int*   Yl = (const int*)d_in[3];
    float* out = (float*)d_out;

    dim3 gcost(Nn / 64, Mm / 64, Bb);
    cost_kernel<<<gcost, 256>>>(X, Y);
    dp_kernel<<<Bb, 512>>>(Xl, Yl, out);
}

// round 3
// speedup vs baseline: 1.2587x; 1.2587x over previous
#include <cuda_runtime.h>
#include <cuda_fp16.h>

#define Bb 32
#define Nn 512
#define Mm 512
#define KD 64
#define NDIAG 1023            // anti-diagonals s = i'+j' in [0, 1022]
#define BIGV 1e10f
#define LOG2E 1.44269504088896340736f
#define LN2   0.69314718055994530942f

// Skewed cost matrix in base-2 units: Danti[b][s][i'] = log2(e) * D[b][i'][s-i']
// fp16: 32 * 1023 * 512 * 2B = 33.5 MB -> fully L2-resident for the handoff.
__device__ __half g_Danti[(size_t)Bb * NDIAG * 512];

__device__ __forceinline__ float ex2f(float x) {
    float r; asm("ex2.approx.f32 %0, %1;" : "=f"(r) : "f"(x)); return r;
}
__device__ __forceinline__ float lg2f(float x) {
    float r; asm("lg2.approx.f32 %0, %1;" : "=f"(r) : "f"(x)); return r;
}

// ---------------------------------------------------------------------------
// Kernel 1: cost matrix, 64x64 tiles, skewed fp16 output, dead tiles skipped
// ---------------------------------------------------------------------------
__global__ __launch_bounds__(256) void cost_kernel(const float* __restrict__ X,
                                                   const float* __restrict__ Y,
                                                   const int* __restrict__ Xl,
                                                   const int* __restrict__ Yl) {
    const int I0 = blockIdx.x * 64;
    const int J0 = blockIdx.y * 64;
    const int b  = blockIdx.z;
    // tiles fully beyond the live region never influence the output
    if (I0 >= Xl[b] || J0 >= Yl[b]) return;

    __shared__ float sm[2 * 64 * 68];   // phase A: Xs+Ys ; phase B: Ds (reused)
    float* Xs = sm;
    float* Ys = sm + 64 * 68;
    float* Ds = sm;                     // 127*65 floats

    const int tid = threadIdx.x;

    {   // float4-coalesced tile loads
        int lr = tid >> 4;
        int lc = (tid & 15) * 4;
        #pragma unroll
        for (int rr = 0; rr < 64; rr += 16) {
            float4 vx = *(const float4*)&X[((size_t)(b * Nn + I0 + lr + rr)) * KD + lc];
            *(float4*)&Xs[(lr + rr) * 68 + lc] = vx;
            float4 vy = *(const float4*)&Y[((size_t)(b * Mm + J0 + lr + rr)) * KD + lc];
            *(float4*)&Ys[(lr + rr) * 68 + lc] = vy;
        }
    }
    __syncthreads();

    const int ty4 = (tid >> 4) * 4;
    const int tx4 = (tid & 15) * 4;
    float acc[4][4];
    #pragma unroll
    for (int r = 0; r < 4; r++)
        #pragma unroll
        for (int c = 0; c < 4; c++) acc[r][c] = 0.f;

    #pragma unroll 4
    for (int k = 0; k < KD; k++) {
        float a[4], bv[4];
        #pragma unroll
        for (int r = 0; r < 4; r++) a[r] = Xs[(ty4 + r) * 68 + k];
        #pragma unroll
        for (int c = 0; c < 4; c++) bv[c] = Ys[(tx4 + c) * 68 + k];
        #pragma unroll
        for (int r = 0; r < 4; r++)
            #pragma unroll
            for (int c = 0; c < 4; c++) {
                float dlt = a[r] - bv[c];
                acc[r][c] = fmaf(dlt, dlt, acc[r][c]);
            }
    }
    __syncthreads();   // smem reads done -> safe to overwrite with Ds

    // scatter into skewed smem tile (scaled to base-2 units)
    #pragma unroll
    for (int r = 0; r < 4; r++)
        #pragma unroll
        for (int c = 0; c < 4; c++) {
            int li = ty4 + r, lj = tx4 + c;
            Ds[(li + lj) * 65 + li] = LOG2E * acc[r][c];
        }
    __syncthreads();

    // coalesced fp16 writes of diagonal segments
    const size_t gbase = (size_t)b * NDIAG * 512;
    const int S0 = I0 + J0;
    for (int idx = tid; idx < 127 * 64; idx += 256) {
        int s  = idx >> 6;
        int li = idx & 63;
        int lj = s - li;
        if (lj >= 0 && lj < 64) {
            g_Danti[gbase + (size_t)(S0 + s) * 512 + (I0 + li)] =
                __float2half(Ds[s * 65 + li]);
        }
    }
}

// ---------------------------------------------------------------------------
// Kernel 2: wavefront DP. One CTA/batch, 512 threads, thread ti owns row i=ti+1.
// Per diagonal: 1 LDS (neighbor's last value), everything else in registers.
// 3-deep D prefetch ring. Base-2 softmin: 3x EX2 + 1x LG2, no scaling FMAs.
// ---------------------------------------------------------------------------
__global__ __launch_bounds__(512) void dp_kernel(const int* __restrict__ Xl,
                                                 const int* __restrict__ Yl,
                                                 float* __restrict__ out) {
    __shared__ float buf[2][520];   // double-buffered current diagonal

    const int b  = blockIdx.x;
    const int ti = threadIdx.x;     // 0..511
    const int i  = ti + 1;

    const int it = Xl[b];
    const int jt = Yl[b];
    const int td = it + jt;         // final diagonal

    buf[1][ti] = BIGV;              // "diagonal 1" values (all BIG)
    __syncthreads();

    const __half* Dp = g_Danti + (size_t)b * NDIAG * 512 + ti;
    __half h0 = Dp[0];              // D for d=2   (s = 0)
    __half h1 = Dp[512];            // D for d=3   (s = 1)

    float prev = BIGV;                        // R[i, j-1] (own last value)
    float nb2  = (ti == 0) ? 0.f : BIGV;      // R[i-1, j-1] (neighbor, 2 diags ago)

    #pragma unroll 2
    for (int d = 2; d <= td; ++d) {
        // prefetch D for iteration d+2 (s = d), ~2 diagonals of latency slack
        int sf = min(d, NDIAG - 1);
        __half hf = Dp[(size_t)sf * 512];

        float nb1 = (ti == 0) ? BIGV : buf[(d - 1) & 1][ti - 1];  // R[i-1, j]

        int  j    = d - i;
        bool live = (j >= 1) && (j <= jt) && (i <= it);
        float val = BIGV;
        if (__any_sync(0xffffffffu, live)) {
            float a  = nb2;
            float bt = nb1;
            float cl = prev;
            float m    = fminf(a, fminf(bt, cl));
            float sum  = ex2f(m - a) + ex2f(m - bt) + ex2f(m - cl);
            float soft = m - lg2f(sum);
            if (live) val = __half2float(h0) + soft;
        }
        buf[d & 1][ti] = val;

        nb2  = nb1;
        prev = val;
        h0 = h1; h1 = hf;
        __syncthreads();
    }

    // thread with i == X_len computed R[X_len, Y_len] at d == td
    if (i == it) out[b] = prev * LN2;
}

// ---------------------------------------------------------------------------
extern "C" void kernel_launch(void* const* d_in, const int* in_sizes, int n_in,
                              void* d_out, int out_size) {
    const float* X  = (const float*)d_in[0];
    const float* Y  = (const float*)d_in[1];
    const int*   Xl = (const int*)d_in[2];
    const int*   Yl = (const int*)d_in[3];
    float* out = (float*)d_out;

    dim3 gcost(Nn / 64, Mm / 64, Bb);
    cost_kernel<<<gcost, 256>>>(X, Y, Xl, Yl);
    dp_kernel<<<Bb, 512>>>(Xl, Yl, out);
}

// round 4
// speedup vs baseline: 1.6978x; 1.3489x over previous
#include <cuda_runtime.h>
#include <cuda_fp16.h>

#define Bb 32
#define Nn 512
#define Mm 512
#define KD 64
#define SPAD 1024             // padded s-extent per row (s = i'+j' in [0,1022])
#define BIGV 1e10f
#define LOG2E 1.44269504088896340736f
#define LN2   0.69314718055994530942f

// Transposed skewed cost matrix, base-2 units:
//   g_D[b][i'][s] = log2(e) * D[b][i'][s-i'],  row stride SPAD halfs.
// 32 * 512 * 1024 * 2B = 33.5 MB (L2-resident handoff).
__device__ __half g_D[(size_t)Bb * Nn * SPAD];

__device__ __forceinline__ float ex2f(float x) {
    float r; asm("ex2.approx.f32 %0, %1;" : "=f"(r) : "f"(x)); return r;
}
__device__ __forceinline__ float lg2f(float x) {
    float r; asm("lg2.approx.f32 %0, %1;" : "=f"(r) : "f"(x)); return r;
}

struct Pack8 { __half h[8]; };

// ---------------------------------------------------------------------------
// Kernel 1: cost matrix, 64x64 tiles. Output layout [b][row][s] lets each
// thread store its 4x4 micro-tile directly (per row, s is contiguous).
// ---------------------------------------------------------------------------
__global__ __launch_bounds__(256) void cost_kernel(const float* __restrict__ X,
                                                   const float* __restrict__ Y,
                                                   const int* __restrict__ Xl,
                                                   const int* __restrict__ Yl) {
    const int I0 = blockIdx.x * 64;
    const int J0 = blockIdx.y * 64;
    const int b  = blockIdx.z;
    if (I0 >= Xl[b] || J0 >= Yl[b]) return;   // dead tile

    __shared__ float Xs[64 * 68];
    __shared__ float Ys[64 * 68];

    const int tid = threadIdx.x;
    {   // float4-coalesced tile loads
        int lr = tid >> 4;
        int lc = (tid & 15) * 4;
        #pragma unroll
        for (int rr = 0; rr < 64; rr += 16) {
            float4 vx = *(const float4*)&X[((size_t)(b * Nn + I0 + lr + rr)) * KD + lc];
            *(float4*)&Xs[(lr + rr) * 68 + lc] = vx;
            float4 vy = *(const float4*)&Y[((size_t)(b * Mm + J0 + lr + rr)) * KD + lc];
            *(float4*)&Ys[(lr + rr) * 68 + lc] = vy;
        }
    }
    __syncthreads();

    const int ty4 = (tid >> 4) * 4;
    const int tx4 = (tid & 15) * 4;
    float acc[4][4];
    #pragma unroll
    for (int r = 0; r < 4; r++)
        #pragma unroll
        for (int c = 0; c < 4; c++) acc[r][c] = 0.f;

    #pragma unroll 4
    for (int k = 0; k < KD; k++) {
        float a[4], bv[4];
        #pragma unroll
        for (int r = 0; r < 4; r++) a[r] = Xs[(ty4 + r) * 68 + k];
        #pragma unroll
        for (int c = 0; c < 4; c++) bv[c] = Ys[(tx4 + c) * 68 + k];
        #pragma unroll
        for (int r = 0; r < 4; r++)
            #pragma unroll
            for (int c = 0; c < 4; c++) {
                float dlt = a[r] - bv[c];
                acc[r][c] = fmaf(dlt, dlt, acc[r][c]);
            }
    }

    // direct stores: row gi = I0+ty4+r, s = gi + (J0+tx4+c)  (contiguous in c)
    #pragma unroll
    for (int r = 0; r < 4; r++) {
        int gi = I0 + ty4 + r;
        __half* dst = g_D + ((size_t)(b * Nn + gi)) * SPAD + (gi + J0 + tx4);
        #pragma unroll
        for (int c = 0; c < 4; c++)
            dst[c] = __float2half(LOG2E * acc[r][c]);
    }
}

// ---------------------------------------------------------------------------
// Kernel 2: wavefront DP. One CTA/batch, 512 threads, thread ti owns row
// i = ti+1 (0-based row ti). D comes in 8-diagonal packs (int4 of fp16) with
// one-block-ahead double buffering -> ~16 periods of load-latency slack.
// Per diagonal: 1 LDS + 1 STS + 1 barrier; softmin = 2x EX2 + 1x LG2.
// ---------------------------------------------------------------------------
__global__ __launch_bounds__(512) void dp_kernel(const int* __restrict__ Xl,
                                                 const int* __restrict__ Yl,
                                                 float* __restrict__ out) {
    __shared__ float buf[2][520];

    const int b  = blockIdx.x;
    const int ti = threadIdx.x;     // 0..511 (row i = ti+1)
    const int i  = ti + 1;

    const int it = Xl[b];
    const int jt = Yl[b];
    const int td = it + jt;                  // final diagonal
    const int dhi = i + jt;                  // live: d > i  &&  d <= dhi
    const bool rowlive = (i <= it);
    const bool isout   = (i == it);

    buf[1][ti] = BIGV;                       // diagonal d=1 values
    __syncthreads();

    const int4* Drow = (const int4*)(g_D + ((size_t)b * Nn + ti) * SPAD);
    int4 cur = Drow[0];                      // s in [0,7]   -> d in [2,9]
    int4 nxt = Drow[1];                      // s in [8,15]  -> d in [10,17]

    float prev = BIGV;                       // R[i, j-1]   (own last value)
    float nb2  = (ti == 0) ? 0.f : BIGV;     // R[i-1, j-1] (neighbor, 2 ago)

    for (int dbase = 2; dbase <= td; dbase += 8) {
        int p = (dbase - 2) >> 3;
        int4 pf = Drow[min(p + 2, SPAD / 8 - 1)];   // pack for dbase+16
        Pack8 pk = *(Pack8*)&cur;

        #pragma unroll
        for (int u = 0; u < 8; ++u) {
            int d = dbase + u;
            if (d > td) break;               // uniform across CTA

            float nb1 = (ti == 0) ? BIGV : buf[(d - 1) & 1][ti - 1];  // R[i-1,j]

            bool live = rowlive && (d > i) && (d <= dhi);
            float val = BIGV;
            if (__any_sync(0xffffffffu, live)) {
                float m  = fminf(nb2, fminf(nb1, prev));
                float da = m - nb2, db = m - nb1, dc = m - prev;   // one is 0
                bool isa = (m == nb2);
                bool isb = (m == nb1);
                float t1 = isa ? db : da;
                float t2 = isa ? dc : (isb ? dc : db);
                float sum  = 1.0f + ex2f(t1) + ex2f(t2);
                float soft = m - lg2f(sum);
                if (live) val = __half2float(pk.h[u]) + soft;
            }
            buf[d & 1][ti] = val;
            if (d == td && isout) out[b] = val * LN2;

            nb2  = nb1;
            prev = val;
            __syncthreads();
        }
        cur = nxt;
        nxt = pf;
    }
}

// ---------------------------------------------------------------------------
extern "C" void kernel_launch(void* const* d_in, const int* in_sizes, int n_in,
                              void* d_out, int out_size) {
    const float* X  = (const float*)d_in[0];
    const float* Y  = (const float*)d_in[1];
    const int*   Xl = (const int*)d_in[2];
    const int*   Yl = (const int*)d_in[3];
    float* out = (float*)d_out;

    dim3 gcost(Nn / 64, Mm / 64, Bb);
    cost_kernel<<<gcost, 256>>>(X, Y, Xl, Yl);
    dp_kernel<<<Bb, 512>>>(Xl, Yl, out);
}